// round 3
// baseline (speedup 1.0000x reference)
#include <cuda_runtime.h>
#include <math.h>

#define Bq 2
#define Sq 2048
#define Eq 1024
#define Hq 16
#define Dq 64
#define Rq (Bq*Sq)          // 4096 rows of x
#define BHq (Bq*Hq)         // 32

// Scratch (static device globals — allocation-free)
__device__ float g_q[BHq*Sq*Dq];   // [B,H,S,D]
__device__ float g_k[BHq*Sq*Dq];
__device__ float g_v[BHq*Sq*Dq];
__device__ float g_g[Rq*Eq];       // [B,S,E]
__device__ float g_o[BHq*Sq*Dq];   // attention out [B,H,S,D]

// ---------------------------------------------------------------------------
// Fused QKVG projection GEMM: Y = X @ W[z], 64x64 tile, 256 threads, 4x4 micro
// z: 0=q, 1=k (scaled by E^-0.5), 2=v, 3=g
// ---------------------------------------------------------------------------
__global__ __launch_bounds__(256) void gemm_kernel(
    const float* __restrict__ X,
    const float* __restrict__ Wqp, const float* __restrict__ Wkp,
    const float* __restrict__ Wvp, const float* __restrict__ Wgp)
{
    const int w = blockIdx.z;
    const float* __restrict__ W = (w==0)?Wqp:(w==1)?Wkp:(w==2)?Wvp:Wgp;

    __shared__ float As[16][64];   // As[k][m]
    __shared__ float Bs[16][64];   // Bs[k][n]

    const int tid = threadIdx.x;
    const int tx = tid & 15, ty = tid >> 4;
    const int row0 = blockIdx.x * 64;
    const int col0 = blockIdx.y * 64;

    // load maps
    const int lar = tid >> 2;            // A row 0..63
    const int lac = (tid & 3) * 4;       // A col quad 0,4,8,12
    const int lbr = tid >> 4;            // B k-row 0..15
    const int lbc = (tid & 15) * 4;      // B col quad

    float acc[4][4] = {};

    for (int k0 = 0; k0 < Eq; k0 += 16) {
        float4 av = *(const float4*)&X[(size_t)(row0+lar)*Eq + k0 + lac];
        As[lac+0][lar]=av.x; As[lac+1][lar]=av.y;
        As[lac+2][lar]=av.z; As[lac+3][lar]=av.w;
        float4 bv = *(const float4*)&W[(size_t)(k0+lbr)*Eq + col0 + lbc];
        *(float4*)&Bs[lbr][lbc] = bv;
        __syncthreads();
        #pragma unroll
        for (int kk = 0; kk < 16; kk++) {
            float4 a = *(const float4*)&As[kk][ty*4];
            float4 b = *(const float4*)&Bs[kk][tx*4];
            acc[0][0]+=a.x*b.x; acc[0][1]+=a.x*b.y; acc[0][2]+=a.x*b.z; acc[0][3]+=a.x*b.w;
            acc[1][0]+=a.y*b.x; acc[1][1]+=a.y*b.y; acc[1][2]+=a.y*b.z; acc[1][3]+=a.y*b.w;
            acc[2][0]+=a.z*b.x; acc[2][1]+=a.z*b.y; acc[2][2]+=a.z*b.z; acc[2][3]+=a.z*b.w;
            acc[3][0]+=a.w*b.x; acc[3][1]+=a.w*b.y; acc[3][2]+=a.w*b.z; acc[3][3]+=a.w*b.w;
        }
        __syncthreads();
    }

    const float kscale = 0.03125f;   // 1024^-0.5
    #pragma unroll
    for (int i = 0; i < 4; i++) {
        const int r = row0 + ty*4 + i;
        #pragma unroll
        for (int j = 0; j < 4; j++) {
            const int c = col0 + tx*4 + j;
            float val = acc[i][j];
            if (w == 3) {
                g_g[(size_t)r*Eq + c] = val;
            } else {
                if (w == 1) val *= kscale;
                const int b = r >> 11, s = r & (Sq-1);
                const int h = c >> 6, d = c & 63;
                float* dst = (w==0) ? g_q : (w==1) ? g_k : g_v;
                dst[(((size_t)(b*Hq+h)*Sq + s) << 6) + d] = val;
            }
        }
    }
}

// ---------------------------------------------------------------------------
// Rotary (theta shift) applied in-place to q and k. One thread per (bh,s,pair)
// ---------------------------------------------------------------------------
__global__ __launch_bounds__(256) void rotary_kernel()
{
    const int idx = blockIdx.x * 256 + threadIdx.x;  // [0, 2M)
    const int j  = idx & 31;           // pair index 0..31
    const int s  = (idx >> 5) & (Sq-1);
    const int bh = idx >> 16;

    const float t = (float)j / 31.0f;
    const float a = 1.0f / powf(10000.0f, t);
    const float arg = (float)s * a;
    float sn, cs;
    sincosf(arg, &sn, &cs);

    const size_t base = (((size_t)bh * Sq + s) << 6) + 2*j;
    float q1 = g_q[base], q2 = g_q[base+1];
    g_q[base]   = q1*cs - q2*sn;
    g_q[base+1] = q2*cs + q1*sn;
    float k1 = g_k[base], k2 = g_k[base+1];
    g_k[base]   = k1*cs - k2*sn;
    g_k[base+1] = k2*cs + k1*sn;
}

// ---------------------------------------------------------------------------
// Flash-style causal retention. Block = 64 q-rows of one (b,h).
// Streams k-tiles of 64; accumulates num = (A.*w)@V and den = sum|A.*w|.
// Mask normalization r factors out; only enters via the clip.
// ---------------------------------------------------------------------------
#define ATT_SMEM ((4096*3 + 64*65) * 4)

__global__ __launch_bounds__(256) void attn_kernel()
{
    extern __shared__ float sm[];
    float* Qs = sm;                 // [d][q]  (transposed)
    float* Ks = sm + 4096;          // [d][k]  (transposed)
    float* Vs = sm + 8192;          // [k][d]
    float* Ps = sm + 12288;         // [q][65]

    const int bh = blockIdx.y;
    const int h  = bh & (Hq-1);
    const int q0 = blockIdx.x * 64;
    const int tid = threadIdx.x;
    const int tx = tid & 15, ty = tid >> 4;

    const float decay = log1pf(-exp2f(-(float)(5+h)));
    const size_t base = (size_t)bh * Sq * Dq;

    // load Q tile, transposed
    {
        const int rr = tid >> 2;
        #pragma unroll
        for (int t = 0; t < 4; t++) {
            const int dd = (tid & 3)*16 + t*4;
            float4 v = *(const float4*)&g_q[base + (size_t)(q0+rr)*64 + dd];
            Qs[(dd+0)*64+rr]=v.x; Qs[(dd+1)*64+rr]=v.y;
            Qs[(dd+2)*64+rr]=v.z; Qs[(dd+3)*64+rr]=v.w;
        }
    }

    float acc[4][4] = {};
    float dsum[4]   = {};
    const int nkt = (q0 >> 6) + 1;

    for (int kt = 0; kt < nkt; kt++) {
        const int k0 = kt * 64;
        __syncthreads();   // protects Qs (1st iter) / Ks,Vs,Ps reuse
        {
            const int rr = tid >> 2;
            #pragma unroll
            for (int t = 0; t < 4; t++) {
                const int dd = (tid & 3)*16 + t*4;
                float4 kv = *(const float4*)&g_k[base + (size_t)(k0+rr)*64 + dd];
                Ks[(dd+0)*64+rr]=kv.x; Ks[(dd+1)*64+rr]=kv.y;
                Ks[(dd+2)*64+rr]=kv.z; Ks[(dd+3)*64+rr]=kv.w;
                float4 vv = *(const float4*)&g_v[base + (size_t)(k0+rr)*64 + dd];
                *(float4*)&Vs[rr*64+dd] = vv;
            }
        }
        __syncthreads();

        float s[4][4] = {};
        #pragma unroll 16
        for (int kk = 0; kk < 64; kk++) {
            float4 a = *(const float4*)&Qs[kk*64 + ty*4];
            float4 b = *(const float4*)&Ks[kk*64 + tx*4];
            s[0][0]+=a.x*b.x; s[0][1]+=a.x*b.y; s[0][2]+=a.x*b.z; s[0][3]+=a.x*b.w;
            s[1][0]+=a.y*b.x; s[1][1]+=a.y*b.y; s[1][2]+=a.y*b.z; s[1][3]+=a.y*b.w;
            s[2][0]+=a.z*b.x; s[2][1]+=a.z*b.y; s[2][2]+=a.z*b.z; s[2][3]+=a.z*b.w;
            s[3][0]+=a.w*b.x; s[3][1]+=a.w*b.y; s[3][2]+=a.w*b.z; s[3][3]+=a.w*b.w;
        }

        #pragma unroll
        for (int i = 0; i < 4; i++) {
            const int qi = q0 + ty*4 + i;
            #pragma unroll
            for (int j = 0; j < 4; j++) {
                const int kj = k0 + tx*4 + j;
                float wgt = (kj <= qi) ? expf((float)(qi-kj)*decay) : 0.0f;
                float p = s[i][j] * wgt;
                dsum[i] += fabsf(p);
                Ps[(ty*4+i)*65 + tx*4+j] = p;
            }
        }
        __syncthreads();

        #pragma unroll 16
        for (int kk = 0; kk < 64; kk++) {
            float4 b = *(const float4*)&Vs[kk*64 + tx*4];
            float p0 = Ps[(ty*4+0)*65+kk];
            float p1 = Ps[(ty*4+1)*65+kk];
            float p2 = Ps[(ty*4+2)*65+kk];
            float p3 = Ps[(ty*4+3)*65+kk];
            acc[0][0]+=p0*b.x; acc[0][1]+=p0*b.y; acc[0][2]+=p0*b.z; acc[0][3]+=p0*b.w;
            acc[1][0]+=p1*b.x; acc[1][1]+=p1*b.y; acc[1][2]+=p1*b.z; acc[1][3]+=p1*b.w;
            acc[2][0]+=p2*b.x; acc[2][1]+=p2*b.y; acc[2][2]+=p2*b.z; acc[2][3]+=p2*b.w;
            acc[3][0]+=p3*b.x; acc[3][1]+=p3*b.y; acc[3][2]+=p3*b.z; acc[3][3]+=p3*b.w;
        }
    }

    // row-abs-sum reduction across the 16 tx lanes (reuse Ps)
    __syncthreads();
    #pragma unroll
    for (int i = 0; i < 4; i++) Ps[(ty*4+i)*65 + tx] = dsum[i];
    __syncthreads();

    const float two_p = exp2f((float)(5+h));
    #pragma unroll
    for (int i = 0; i < 4; i++) {
        const int row = ty*4 + i;
        const int qi  = q0 + row;
        float dtot = 0.0f;
        #pragma unroll
        for (int t = 0; t < 16; t++) dtot += Ps[row*65 + t];
        // r = 1/sqrt(geometric decay sum) (closed form)
        const float geo = -expm1f((float)(qi+1) * decay) * two_p;
        const float r   = rsqrtf(geo);
        float den = r * dtot;
        den = fminf(fmaxf(den, 1.0f), 50000.0f);
        const float sc = r / den;
        #pragma unroll
        for (int j = 0; j < 4; j++)
            g_o[base + (size_t)qi*64 + tx*4 + j] = acc[i][j] * sc;
    }
}

// ---------------------------------------------------------------------------
// Epilogue: per-head RMSNorm over D, gate with silu(g). One warp per (b,s,h).
// ---------------------------------------------------------------------------
__global__ __launch_bounds__(256) void epilogue_kernel(float* __restrict__ out)
{
    const int gid  = blockIdx.x * 8 + (threadIdx.x >> 5);  // 0..65535
    const int lane = threadIdx.x & 31;
    const int h = gid & (Hq-1);
    const int s = (gid >> 4) & (Sq-1);
    const int b = gid >> 15;

    const float* op = &g_o[(((size_t)(b*Hq+h)*Sq) + s) * 64];
    float v1 = op[lane], v2 = op[lane+32];
    float ss = v1*v1 + v2*v2;
    #pragma unroll
    for (int o = 16; o; o >>= 1) ss += __shfl_xor_sync(0xffffffffu, ss, o);
    const float sc = rsqrtf(ss * (1.0f/64.0f) + 1e-6f);

    const size_t ob = ((size_t)(b*Sq + s))*Eq + h*64;
    float gv1 = g_g[ob+lane], gv2 = g_g[ob+lane+32];
    out[ob+lane]    = (gv1 / (1.0f + expf(-gv1))) * v1 * sc;
    out[ob+lane+32] = (gv2 / (1.0f + expf(-gv2))) * v2 * sc;
}

// ---------------------------------------------------------------------------
extern "C" void kernel_launch(void* const* d_in, const int* in_sizes, int n_in,
                              void* d_out, int out_size)
{
    const float* x  = (const float*)d_in[0];
    const float* Wq = (const float*)d_in[1];
    const float* Wk = (const float*)d_in[2];
    const float* Wv = (const float*)d_in[3];
    const float* Wg = (const float*)d_in[4];
    float* out = (float*)d_out;

    cudaFuncSetAttribute(attn_kernel,
                         cudaFuncAttributeMaxDynamicSharedMemorySize, ATT_SMEM);

    gemm_kernel<<<dim3(Rq/64, Eq/64, 4), 256>>>(x, Wq, Wk, Wv, Wg);
    rotary_kernel<<<(BHq*Sq*32)/256, 256>>>();
    attn_kernel<<<dim3(Sq/64, BHq), 256, ATT_SMEM>>>();
    epilogue_kernel<<<(Bq*Sq*Hq)/8, 256>>>(out);
}

// round 5
// speedup vs baseline: 1.4675x; 1.4675x over previous
#include <cuda_runtime.h>
#include <cuda_bf16.h>
#include <math.h>
#include <stdint.h>

#define Bq 2
#define Sq 2048
#define Eq 1024
#define Hq 16
#define Dq 64
#define Rq (Bq*Sq)          // 4096 rows of x
#define BHq (Bq*Hq)         // 32

// Scratch (static device globals — allocation-free)
__device__ float g_q[BHq*Sq*Dq];   // [B,H,S,D]
__device__ float g_k[BHq*Sq*Dq];
__device__ float g_v[BHq*Sq*Dq];
__device__ float g_g[Rq*Eq];       // [B,S,E]
__device__ float g_o[BHq*Sq*Dq];   // attention out [B,H,S,D]
__device__ float g_wt[4*Eq*Eq];    // transposed weights WT[n][k]

__device__ __forceinline__ uint32_t smem_u32(const void* p) {
    uint32_t a;
    asm("{ .reg .u64 t; cvta.to.shared.u64 t, %1; cvt.u32.u64 %0, t; }"
        : "=r"(a) : "l"(p));
    return a;
}

#define LDSM4(r, addr) \
    asm volatile("ldmatrix.sync.aligned.m8n8.x4.shared.b16 {%0,%1,%2,%3}, [%4];" \
        : "=r"((r)[0]), "=r"((r)[1]), "=r"((r)[2]), "=r"((r)[3]) : "r"(addr))

#define MMA16816(c, a, b0, b1) \
    asm volatile("mma.sync.aligned.m16n8k16.row.col.f32.bf16.bf16.f32 " \
        "{%0,%1,%2,%3},{%4,%5,%6,%7},{%8,%9},{%0,%1,%2,%3};" \
        : "+f"((c)[0]), "+f"((c)[1]), "+f"((c)[2]), "+f"((c)[3]) \
        : "r"((a)[0]), "r"((a)[1]), "r"((a)[2]), "r"((a)[3]), "r"(b0), "r"(b1))

// ===========================================================================
// Transpose kernel: g_wt[z][n*1024+k] = W[z][k*1024+n]
// ===========================================================================
__global__ __launch_bounds__(256) void transpose_kernel(
    const float* __restrict__ Wqp, const float* __restrict__ Wkp,
    const float* __restrict__ Wvp, const float* __restrict__ Wgp)
{
    const int z = blockIdx.z;
    const float* __restrict__ W = (z==0)?Wqp:(z==1)?Wkp:(z==2)?Wvp:Wgp;
    float* __restrict__ WT = g_wt + (size_t)z * Eq * Eq;

    __shared__ float t[32][33];
    const int tx = threadIdx.x & 31, ty = threadIdx.x >> 5;   // 32 x 8
    const int x0 = blockIdx.x * 32, y0 = blockIdx.y * 32;

    #pragma unroll
    for (int r = 0; r < 32; r += 8)
        t[ty + r][tx] = W[(size_t)(y0 + ty + r) * Eq + x0 + tx];
    __syncthreads();
    #pragma unroll
    for (int r = 0; r < 32; r += 8)
        WT[(size_t)(x0 + ty + r) * Eq + y0 + tx] = t[tx][ty + r];
}

// ===========================================================================
// mma.sync split-bf16 GEMM: Y[4096,1024] = X @ W[z], 128x128 CTA tile.
// 3-term split: a*b ~= ah*bh + ah*bl + al*bh (lo*lo dropped, ~2^-32 rel).
// 8 warps of 64x32; K-chunks of 32 fp32; double-buffered SMEM.
// SMEM tiles (per buffer): Ah, Al, Bh, Bl each 128 rows x 40 halves (80B row,
// 32 data halves + 8 pad -> conflict-free ldmatrix at stride 80).
// ===========================================================================
#define TILE_B   10240               // 128*80 bytes
#define BUF_B    (4*TILE_B)          // 40960
#define GEMM_SMEM (2*BUF_B)          // 81920

__device__ __forceinline__ void ldg_chunk(const float* __restrict__ X,
                                          const float* __restrict__ Wt,
                                          int row0, int col0, int c, int tid,
                                          float4* ra, float4* rb)
{
    #pragma unroll
    for (int it = 0; it < 4; it++) {
        const int idx = it * 256 + tid;
        const int m = idx >> 3, kq = idx & 7;
        ra[it] = *(const float4*)&X [(size_t)(row0 + m) * Eq + c * 32 + kq * 4];
        rb[it] = *(const float4*)&Wt[(size_t)(col0 + m) * Eq + c * 32 + kq * 4];
    }
}

__device__ __forceinline__ void split4(float4 v, uint2& h, uint2& l) {
    const float fv[4] = {v.x, v.y, v.z, v.w};
    uint32_t hh[4], ll[4];
    #pragma unroll
    for (int u = 0; u < 4; u++) {
        __nv_bfloat16 bh = __float2bfloat16(fv[u]);
        float res = fv[u] - __bfloat162float(bh);
        __nv_bfloat16 bl = __float2bfloat16(res);
        hh[u] = (uint32_t)__bfloat16_as_ushort(bh);
        ll[u] = (uint32_t)__bfloat16_as_ushort(bl);
    }
    h.x = hh[0] | (hh[1] << 16);  h.y = hh[2] | (hh[3] << 16);
    l.x = ll[0] | (ll[1] << 16);  l.y = ll[2] | (ll[3] << 16);
}

__device__ __forceinline__ void store_chunk(char* buf, int tid,
                                            const float4* ra, const float4* rb)
{
    #pragma unroll
    for (int it = 0; it < 4; it++) {
        const int idx = it * 256 + tid;
        const int m = idx >> 3, kq = idx & 7;
        const int off = m * 80 + kq * 8;
        uint2 h, l;
        split4(ra[it], h, l);
        *(uint2*)(buf + off)              = h;   // Ah
        *(uint2*)(buf + TILE_B + off)     = l;   // Al
        split4(rb[it], h, l);
        *(uint2*)(buf + 2*TILE_B + off)   = h;   // Bh
        *(uint2*)(buf + 3*TILE_B + off)   = l;   // Bl
    }
}

__global__ __launch_bounds__(256) void gemm_mma_kernel(const float* __restrict__ X)
{
    extern __shared__ char smc[];
    const int tid = threadIdx.x, lane = tid & 31, wrp = tid >> 5;
    const int wm = wrp & 1, wn = wrp >> 1;          // 2x4 warp grid: 64x32 each
    const int row0 = blockIdx.x * 128;
    const int col0 = blockIdx.y * 128;
    const int w    = blockIdx.z;
    const float* __restrict__ Wt = g_wt + (size_t)w * Eq * Eq;

    const uint32_t sbase = smem_u32(smc);
    // ldmatrix lane offsets (bytes within a tile)
    const uint32_t aoff = (uint32_t)((wm*64 + (lane & 15)) * 80 + (lane >> 4) * 16);
    const uint32_t boff = (uint32_t)((wn*32 + (lane & 7) + ((lane >> 4) & 1) * 8) * 80
                                     + ((lane >> 3) & 1) * 16);

    float acc[4][4][4] = {};

    float4 ra[4], rb[4];
    ldg_chunk(X, Wt, row0, col0, 0, tid, ra, rb);
    store_chunk(smc, tid, ra, rb);
    __syncthreads();

    for (int c = 0; c < 32; c++) {
        if (c < 31) ldg_chunk(X, Wt, row0, col0, c + 1, tid, ra, rb);

        const uint32_t base = sbase + (uint32_t)((c & 1) * BUF_B);
        #pragma unroll
        for (int ks = 0; ks < 2; ks++) {
            const uint32_t ksb = (uint32_t)(ks * 32);
            uint32_t a_h[4][4], a_l[4][4], b_h[4][2], b_l[4][2];
            #pragma unroll
            for (int mt = 0; mt < 4; mt++)
                LDSM4(a_h[mt], base + aoff + mt*1280 + ksb);
            #pragma unroll
            for (int np = 0; np < 2; np++) {
                uint32_t r[4];
                LDSM4(r, base + 2*TILE_B + boff + np*1280 + ksb);
                b_h[2*np][0] = r[0]; b_h[2*np][1] = r[1];
                b_h[2*np+1][0] = r[2]; b_h[2*np+1][1] = r[3];
            }
            #pragma unroll
            for (int mt = 0; mt < 4; mt++)
                #pragma unroll
                for (int nt = 0; nt < 4; nt++)
                    MMA16816(acc[mt][nt], a_h[mt], b_h[nt][0], b_h[nt][1]);

            #pragma unroll
            for (int mt = 0; mt < 4; mt++)
                LDSM4(a_l[mt], base + TILE_B + aoff + mt*1280 + ksb);
            #pragma unroll
            for (int mt = 0; mt < 4; mt++)
                #pragma unroll
                for (int nt = 0; nt < 4; nt++)
                    MMA16816(acc[mt][nt], a_l[mt], b_h[nt][0], b_h[nt][1]);

            #pragma unroll
            for (int np = 0; np < 2; np++) {
                uint32_t r[4];
                LDSM4(r, base + 3*TILE_B + boff + np*1280 + ksb);
                b_l[2*np][0] = r[0]; b_l[2*np][1] = r[1];
                b_l[2*np+1][0] = r[2]; b_l[2*np+1][1] = r[3];
            }
            #pragma unroll
            for (int mt = 0; mt < 4; mt++)
                #pragma unroll
                for (int nt = 0; nt < 4; nt++)
                    MMA16816(acc[mt][nt], a_h[mt], b_l[nt][0], b_l[nt][1]);
        }

        if (c < 31) store_chunk(smc + ((c + 1) & 1) * BUF_B, tid, ra, rb);
        __syncthreads();
    }

    // Epilogue: scatter accumulators
    const int r_in = lane >> 2;
    const int c_in = (lane & 3) * 2;
    const float sc = (w == 1) ? 0.03125f : 1.0f;   // k scaled by E^-0.5

    #pragma unroll
    for (int mt = 0; mt < 4; mt++) {
        #pragma unroll
        for (int nt = 0; nt < 4; nt++) {
            const int m0  = row0 + wm*64 + mt*16 + r_in;
            const int col = col0 + wn*32 + nt*8 + c_in;
            if (w == 3) {
                *(float2*)&g_g[(size_t)m0 * Eq + col] =
                    make_float2(acc[mt][nt][0], acc[mt][nt][1]);
                *(float2*)&g_g[(size_t)(m0+8) * Eq + col] =
                    make_float2(acc[mt][nt][2], acc[mt][nt][3]);
            } else {
                const int h = col >> 6, d = col & 63;
                float* dst = (w == 0) ? g_q : (w == 1) ? g_k : g_v;
                const int b0 = m0 >> 11, s0 = m0 & (Sq-1);
                *(float2*)&dst[(((size_t)(b0*Hq + h) * Sq + s0) << 6) + d] =
                    make_float2(acc[mt][nt][0] * sc, acc[mt][nt][1] * sc);
                const int m1 = m0 + 8;
                const int b1 = m1 >> 11, s1 = m1 & (Sq-1);
                *(float2*)&dst[(((size_t)(b1*Hq + h) * Sq + s1) << 6) + d] =
                    make_float2(acc[mt][nt][2] * sc, acc[mt][nt][3] * sc);
            }
        }
    }
}

// ---------------------------------------------------------------------------
// Rotary (theta shift) applied in-place to q and k. One thread per (bh,s,pair)
// ---------------------------------------------------------------------------
__global__ __launch_bounds__(256) void rotary_kernel()
{
    const int idx = blockIdx.x * 256 + threadIdx.x;  // [0, 2M)
    const int j  = idx & 31;           // pair index 0..31
    const int s  = (idx >> 5) & (Sq-1);
    const int bh = idx >> 16;

    const float t = (float)j / 31.0f;
    const float a = 1.0f / powf(10000.0f, t);
    const float arg = (float)s * a;
    float sn, cs;
    sincosf(arg, &sn, &cs);

    const size_t base = (((size_t)bh * Sq + s) << 6) + 2*j;
    float q1 = g_q[base], q2 = g_q[base+1];
    g_q[base]   = q1*cs - q2*sn;
    g_q[base+1] = q2*cs + q1*sn;
    float k1 = g_k[base], k2 = g_k[base+1];
    g_k[base]   = k1*cs - k2*sn;
    g_k[base+1] = k2*cs + k1*sn;
}

// ---------------------------------------------------------------------------
// Flash-style causal retention. Block = 64 q-rows of one (b,h).
// ---------------------------------------------------------------------------
#define ATT_SMEM ((4096*3 + 64*65) * 4)

__global__ __launch_bounds__(256) void attn_kernel()
{
    extern __shared__ float sm[];
    float* Qs = sm;                 // [d][q]  (transposed)
    float* Ks = sm + 4096;          // [d][k]  (transposed)
    float* Vs = sm + 8192;          // [k][d]
    float* Ps = sm + 12288;         // [q][65]

    const int bh = blockIdx.y;
    const int h  = bh & (Hq-1);
    const int q0 = blockIdx.x * 64;
    const int tid = threadIdx.x;
    const int tx = tid & 15, ty = tid >> 4;

    const float decay = log1pf(-exp2f(-(float)(5+h)));
    const size_t base = (size_t)bh * Sq * Dq;

    // load Q tile, transposed
    {
        const int rr = tid >> 2;
        #pragma unroll
        for (int t = 0; t < 4; t++) {
            const int dd = (tid & 3)*16 + t*4;
            float4 v = *(const float4*)&g_q[base + (size_t)(q0+rr)*64 + dd];
            Qs[(dd+0)*64+rr]=v.x; Qs[(dd+1)*64+rr]=v.y;
            Qs[(dd+2)*64+rr]=v.z; Qs[(dd+3)*64+rr]=v.w;
        }
    }

    float acc[4][4] = {};
    float dsum[4]   = {};
    const int nkt = (q0 >> 6) + 1;

    for (int kt = 0; kt < nkt; kt++) {
        const int k0 = kt * 64;
        __syncthreads();
        {
            const int rr = tid >> 2;
            #pragma unroll
            for (int t = 0; t < 4; t++) {
                const int dd = (tid & 3)*16 + t*4;
                float4 kv = *(const float4*)&g_k[base + (size_t)(k0+rr)*64 + dd];
                Ks[(dd+0)*64+rr]=kv.x; Ks[(dd+1)*64+rr]=kv.y;
                Ks[(dd+2)*64+rr]=kv.z; Ks[(dd+3)*64+rr]=kv.w;
                float4 vv = *(const float4*)&g_v[base + (size_t)(k0+rr)*64 + dd];
                *(float4*)&Vs[rr*64+dd] = vv;
            }
        }
        __syncthreads();

        float s[4][4] = {};
        #pragma unroll 16
        for (int kk = 0; kk < 64; kk++) {
            float4 a = *(const float4*)&Qs[kk*64 + ty*4];
            float4 b = *(const float4*)&Ks[kk*64 + tx*4];
            s[0][0]+=a.x*b.x; s[0][1]+=a.x*b.y; s[0][2]+=a.x*b.z; s[0][3]+=a.x*b.w;
            s[1][0]+=a.y*b.x; s[1][1]+=a.y*b.y; s[1][2]+=a.y*b.z; s[1][3]+=a.y*b.w;
            s[2][0]+=a.z*b.x; s[2][1]+=a.z*b.y; s[2][2]+=a.z*b.z; s[2][3]+=a.z*b.w;
            s[3][0]+=a.w*b.x; s[3][1]+=a.w*b.y; s[3][2]+=a.w*b.z; s[3][3]+=a.w*b.w;
        }

        #pragma unroll
        for (int i = 0; i < 4; i++) {
            const int qi = q0 + ty*4 + i;
            #pragma unroll
            for (int j = 0; j < 4; j++) {
                const int kj = k0 + tx*4 + j;
                float wgt = (kj <= qi) ? expf((float)(qi-kj)*decay) : 0.0f;
                float p = s[i][j] * wgt;
                dsum[i] += fabsf(p);
                Ps[(ty*4+i)*65 + tx*4+j] = p;
            }
        }
        __syncthreads();

        #pragma unroll 16
        for (int kk = 0; kk < 64; kk++) {
            float4 b = *(const float4*)&Vs[kk*64 + tx*4];
            float p0 = Ps[(ty*4+0)*65+kk];
            float p1 = Ps[(ty*4+1)*65+kk];
            float p2 = Ps[(ty*4+2)*65+kk];
            float p3 = Ps[(ty*4+3)*65+kk];
            acc[0][0]+=p0*b.x; acc[0][1]+=p0*b.y; acc[0][2]+=p0*b.z; acc[0][3]+=p0*b.w;
            acc[1][0]+=p1*b.x; acc[1][1]+=p1*b.y; acc[1][2]+=p1*b.z; acc[1][3]+=p1*b.w;
            acc[2][0]+=p2*b.x; acc[2][1]+=p2*b.y; acc[2][2]+=p2*b.z; acc[2][3]+=p2*b.w;
            acc[3][0]+=p3*b.x; acc[3][1]+=p3*b.y; acc[3][2]+=p3*b.z; acc[3][3]+=p3*b.w;
        }
    }

    // row-abs-sum reduction across the 16 tx lanes (reuse Ps)
    __syncthreads();
    #pragma unroll
    for (int i = 0; i < 4; i++) Ps[(ty*4+i)*65 + tx] = dsum[i];
    __syncthreads();

    const float two_p = exp2f((float)(5+h));
    #pragma unroll
    for (int i = 0; i < 4; i++) {
        const int row = ty*4 + i;
        const int qi  = q0 + row;
        float dtot = 0.0f;
        #pragma unroll
        for (int t = 0; t < 16; t++) dtot += Ps[row*65 + t];
        const float geo = -expm1f((float)(qi+1) * decay) * two_p;
        const float r   = rsqrtf(geo);
        float den = r * dtot;
        den = fminf(fmaxf(den, 1.0f), 50000.0f);
        const float sc = r / den;
        #pragma unroll
        for (int j = 0; j < 4; j++)
            g_o[base + (size_t)qi*64 + tx*4 + j] = acc[i][j] * sc;
    }
}

// ---------------------------------------------------------------------------
// Epilogue: per-head RMSNorm over D, gate with silu(g). One warp per (b,s,h).
// ---------------------------------------------------------------------------
__global__ __launch_bounds__(256) void epilogue_kernel(float* __restrict__ out)
{
    const int gid  = blockIdx.x * 8 + (threadIdx.x >> 5);  // 0..65535
    const int lane = threadIdx.x & 31;
    const int h = gid & (Hq-1);
    const int s = (gid >> 4) & (Sq-1);
    const int b = gid >> 15;

    const float* op = &g_o[(((size_t)(b*Hq+h)*Sq) + s) * 64];
    float v1 = op[lane], v2 = op[lane+32];
    float ss = v1*v1 + v2*v2;
    #pragma unroll
    for (int o = 16; o; o >>= 1) ss += __shfl_xor_sync(0xffffffffu, ss, o);
    const float sc = rsqrtf(ss * (1.0f/64.0f) + 1e-6f);

    const size_t ob = ((size_t)(b*Sq + s))*Eq + h*64;
    float gv1 = g_g[ob+lane], gv2 = g_g[ob+lane+32];
    out[ob+lane]    = (gv1 / (1.0f + expf(-gv1))) * v1 * sc;
    out[ob+lane+32] = (gv2 / (1.0f + expf(-gv2))) * v2 * sc;
}

// ---------------------------------------------------------------------------
extern "C" void kernel_launch(void* const* d_in, const int* in_sizes, int n_in,
                              void* d_out, int out_size)
{
    const float* x  = (const float*)d_in[0];
    const float* Wq = (const float*)d_in[1];
    const float* Wk = (const float*)d_in[2];
    const float* Wv = (const float*)d_in[3];
    const float* Wg = (const float*)d_in[4];
    float* out = (float*)d_out;

    cudaFuncSetAttribute(attn_kernel,
                         cudaFuncAttributeMaxDynamicSharedMemorySize, ATT_SMEM);
    cudaFuncSetAttribute(gemm_mma_kernel,
                         cudaFuncAttributeMaxDynamicSharedMemorySize, GEMM_SMEM);

    transpose_kernel<<<dim3(32, 32, 4), 256>>>(Wq, Wk, Wv, Wg);
    gemm_mma_kernel<<<dim3(Rq/128, Eq/128, 4), 256, GEMM_SMEM>>>(x);
    rotary_kernel<<<(BHq*Sq*32)/256, 256>>>();
    attn_kernel<<<dim3(Sq/64, BHq), 256, ATT_SMEM>>>();
    epilogue_kernel<<<(Bq*Sq*Hq)/8, 256>>>(out);
}

// round 10
// speedup vs baseline: 2.5242x; 1.7201x over previous
#include <cuda_runtime.h>
#include <cuda_bf16.h>
#include <math.h>
#include <stdint.h>

#define Bq 2
#define Sq 2048
#define Eq 1024
#define Hq 16
#define Dq 64
#define Rq (Bq*Sq)          // 4096 rows of x
#define BHq (Bq*Hq)         // 32

// Scratch (static device globals — allocation-free)
__device__ float g_q[BHq*Sq*Dq];   // [B,H,S,D]
__device__ float g_k[BHq*Sq*Dq];
__device__ float g_v[BHq*Sq*Dq];
__device__ float g_g[Rq*Eq];       // [B,S,E]
__device__ float g_o[BHq*Sq*Dq];   // attention out [B,H,S,D]
__device__ float g_wt[4*Eq*Eq];    // transposed weights WT[n][k]

__device__ __forceinline__ uint32_t smem_u32(const void* p) {
    uint32_t a;
    asm("{ .reg .u64 t; cvta.to.shared.u64 t, %1; cvt.u32.u64 %0, t; }"
        : "=r"(a) : "l"(p));
    return a;
}

#define LDSM4(r, addr) \
    asm volatile("ldmatrix.sync.aligned.m8n8.x4.shared.b16 {%0,%1,%2,%3}, [%4];" \
        : "=r"((r)[0]), "=r"((r)[1]), "=r"((r)[2]), "=r"((r)[3]) : "r"(addr))

#define LDSM4T(r, addr) \
    asm volatile("ldmatrix.sync.aligned.m8n8.x4.trans.shared.b16 {%0,%1,%2,%3}, [%4];" \
        : "=r"((r)[0]), "=r"((r)[1]), "=r"((r)[2]), "=r"((r)[3]) : "r"(addr))

#define MMA16816(c, a, b0, b1) \
    asm volatile("mma.sync.aligned.m16n8k16.row.col.f32.bf16.bf16.f32 " \
        "{%0,%1,%2,%3},{%4,%5,%6,%7},{%8,%9},{%0,%1,%2,%3};" \
        : "+f"((c)[0]), "+f"((c)[1]), "+f"((c)[2]), "+f"((c)[3]) \
        : "r"((a)[0]), "r"((a)[1]), "r"((a)[2]), "r"((a)[3]), "r"(b0), "r"(b1))

__device__ __forceinline__ void split4(float4 v, uint2& h, uint2& l) {
    const float fv[4] = {v.x, v.y, v.z, v.w};
    uint32_t hh[4], ll[4];
    #pragma unroll
    for (int u = 0; u < 4; u++) {
        __nv_bfloat16 bh = __float2bfloat16(fv[u]);
        float res = fv[u] - __bfloat162float(bh);
        __nv_bfloat16 bl = __float2bfloat16(res);
        hh[u] = (uint32_t)__bfloat16_as_ushort(bh);
        ll[u] = (uint32_t)__bfloat16_as_ushort(bl);
    }
    h.x = hh[0] | (hh[1] << 16);  h.y = hh[2] | (hh[3] << 16);
    l.x = ll[0] | (ll[1] << 16);  l.y = ll[2] | (ll[3] << 16);
}

__device__ __forceinline__ void split_pair(float a, float b,
                                           uint32_t& h, uint32_t& l) {
    __nv_bfloat162 hv = __floats2bfloat162_rn(a, b);
    float ra = a - __bfloat162float(hv.x);
    float rb = b - __bfloat162float(hv.y);
    __nv_bfloat162 lv = __floats2bfloat162_rn(ra, rb);
    h = *(uint32_t*)&hv;
    l = *(uint32_t*)&lv;
}

// ===========================================================================
// Transpose kernel: g_wt[z][n*1024+k] = W[z][k*1024+n]
// ===========================================================================
__global__ __launch_bounds__(256) void transpose_kernel(
    const float* __restrict__ Wqp, const float* __restrict__ Wkp,
    const float* __restrict__ Wvp, const float* __restrict__ Wgp)
{
    const int z = blockIdx.z;
    const float* __restrict__ W = (z==0)?Wqp:(z==1)?Wkp:(z==2)?Wvp:Wgp;
    float* __restrict__ WT = g_wt + (size_t)z * Eq * Eq;

    __shared__ float t[32][33];
    const int tx = threadIdx.x & 31, ty = threadIdx.x >> 5;   // 32 x 8
    const int x0 = blockIdx.x * 32, y0 = blockIdx.y * 32;

    #pragma unroll
    for (int r = 0; r < 32; r += 8)
        t[ty + r][tx] = W[(size_t)(y0 + ty + r) * Eq + x0 + tx];
    __syncthreads();
    #pragma unroll
    for (int r = 0; r < 32; r += 8)
        WT[(size_t)(x0 + ty + r) * Eq + y0 + tx] = t[tx][ty + r];
}

// ===========================================================================
// mma.sync split-bf16 GEMM (identical to R5 passing version)
// ===========================================================================
#define TILE_B   10240               // 128*80 bytes
#define BUF_B    (4*TILE_B)          // 40960
#define GEMM_SMEM (2*BUF_B)          // 81920

__device__ __forceinline__ void ldg_chunk(const float* __restrict__ X,
                                          const float* __restrict__ Wt,
                                          int row0, int col0, int c, int tid,
                                          float4* ra, float4* rb)
{
    #pragma unroll
    for (int it = 0; it < 4; it++) {
        const int idx = it * 256 + tid;
        const int m = idx >> 3, kq = idx & 7;
        ra[it] = *(const float4*)&X [(size_t)(row0 + m) * Eq + c * 32 + kq * 4];
        rb[it] = *(const float4*)&Wt[(size_t)(col0 + m) * Eq + c * 32 + kq * 4];
    }
}

__device__ __forceinline__ void store_chunk(char* buf, int tid,
                                            const float4* ra, const float4* rb)
{
    #pragma unroll
    for (int it = 0; it < 4; it++) {
        const int idx = it * 256 + tid;
        const int m = idx >> 3, kq = idx & 7;
        const int off = m * 80 + kq * 8;
        uint2 h, l;
        split4(ra[it], h, l);
        *(uint2*)(buf + off)              = h;   // Ah
        *(uint2*)(buf + TILE_B + off)     = l;   // Al
        split4(rb[it], h, l);
        *(uint2*)(buf + 2*TILE_B + off)   = h;   // Bh
        *(uint2*)(buf + 3*TILE_B + off)   = l;   // Bl
    }
}

__global__ __launch_bounds__(256) void gemm_mma_kernel(const float* __restrict__ X)
{
    extern __shared__ char smc[];
    const int tid = threadIdx.x, lane = tid & 31, wrp = tid >> 5;
    const int wm = wrp & 1, wn = wrp >> 1;          // 2x4 warp grid: 64x32 each
    const int row0 = blockIdx.x * 128;
    const int col0 = blockIdx.y * 128;
    const int w    = blockIdx.z;
    const float* __restrict__ Wt = g_wt + (size_t)w * Eq * Eq;

    const uint32_t sbase = smem_u32(smc);
    const uint32_t aoff = (uint32_t)((wm*64 + (lane & 15)) * 80 + (lane >> 4) * 16);
    const uint32_t boff = (uint32_t)((wn*32 + (lane & 7) + ((lane >> 4) & 1) * 8) * 80
                                     + ((lane >> 3) & 1) * 16);

    float acc[4][4][4] = {};

    float4 ra[4], rb[4];
    ldg_chunk(X, Wt, row0, col0, 0, tid, ra, rb);
    store_chunk(smc, tid, ra, rb);
    __syncthreads();

    for (int c = 0; c < 32; c++) {
        if (c < 31) ldg_chunk(X, Wt, row0, col0, c + 1, tid, ra, rb);

        const uint32_t base = sbase + (uint32_t)((c & 1) * BUF_B);
        #pragma unroll
        for (int ks = 0; ks < 2; ks++) {
            const uint32_t ksb = (uint32_t)(ks * 32);
            uint32_t a_h[4][4], a_l[4][4], b_h[4][2], b_l[4][2];
            #pragma unroll
            for (int mt = 0; mt < 4; mt++)
                LDSM4(a_h[mt], base + aoff + mt*1280 + ksb);
            #pragma unroll
            for (int np = 0; np < 2; np++) {
                uint32_t r[4];
                LDSM4(r, base + 2*TILE_B + boff + np*1280 + ksb);
                b_h[2*np][0] = r[0]; b_h[2*np][1] = r[1];
                b_h[2*np+1][0] = r[2]; b_h[2*np+1][1] = r[3];
            }
            #pragma unroll
            for (int mt = 0; mt < 4; mt++)
                #pragma unroll
                for (int nt = 0; nt < 4; nt++)
                    MMA16816(acc[mt][nt], a_h[mt], b_h[nt][0], b_h[nt][1]);

            #pragma unroll
            for (int mt = 0; mt < 4; mt++)
                LDSM4(a_l[mt], base + TILE_B + aoff + mt*1280 + ksb);
            #pragma unroll
            for (int mt = 0; mt < 4; mt++)
                #pragma unroll
                for (int nt = 0; nt < 4; nt++)
                    MMA16816(acc[mt][nt], a_l[mt], b_h[nt][0], b_h[nt][1]);

            #pragma unroll
            for (int np = 0; np < 2; np++) {
                uint32_t r[4];
                LDSM4(r, base + 3*TILE_B + boff + np*1280 + ksb);
                b_l[2*np][0] = r[0]; b_l[2*np][1] = r[1];
                b_l[2*np+1][0] = r[2]; b_l[2*np+1][1] = r[3];
            }
            #pragma unroll
            for (int mt = 0; mt < 4; mt++)
                #pragma unroll
                for (int nt = 0; nt < 4; nt++)
                    MMA16816(acc[mt][nt], a_h[mt], b_l[nt][0], b_l[nt][1]);
        }

        if (c < 31) store_chunk(smc + ((c + 1) & 1) * BUF_B, tid, ra, rb);
        __syncthreads();
    }

    const int r_in = lane >> 2;
    const int c_in = (lane & 3) * 2;
    const float sc = (w == 1) ? 0.03125f : 1.0f;   // k scaled by E^-0.5

    #pragma unroll
    for (int mt = 0; mt < 4; mt++) {
        #pragma unroll
        for (int nt = 0; nt < 4; nt++) {
            const int m0  = row0 + wm*64 + mt*16 + r_in;
            const int col = col0 + wn*32 + nt*8 + c_in;
            if (w == 3) {
                *(float2*)&g_g[(size_t)m0 * Eq + col] =
                    make_float2(acc[mt][nt][0], acc[mt][nt][1]);
                *(float2*)&g_g[(size_t)(m0+8) * Eq + col] =
                    make_float2(acc[mt][nt][2], acc[mt][nt][3]);
            } else {
                const int h = col >> 6, d = col & 63;
                float* dst = (w == 0) ? g_q : (w == 1) ? g_k : g_v;
                const int b0 = m0 >> 11, s0 = m0 & (Sq-1);
                *(float2*)&dst[(((size_t)(b0*Hq + h) * Sq + s0) << 6) + d] =
                    make_float2(acc[mt][nt][0] * sc, acc[mt][nt][1] * sc);
                const int m1 = m0 + 8;
                const int b1 = m1 >> 11, s1 = m1 & (Sq-1);
                *(float2*)&dst[(((size_t)(b1*Hq + h) * Sq + s1) << 6) + d] =
                    make_float2(acc[mt][nt][2] * sc, acc[mt][nt][3] * sc);
            }
        }
    }
}

// ---------------------------------------------------------------------------
// Rotary (theta shift) applied in-place to q and k. One thread per (bh,s,pair)
// ---------------------------------------------------------------------------
__global__ __launch_bounds__(256) void rotary_kernel()
{
    const int idx = blockIdx.x * 256 + threadIdx.x;  // [0, 2M)
    const int j  = idx & 31;           // pair index 0..31
    const int s  = (idx >> 5) & (Sq-1);
    const int bh = idx >> 16;

    const float t = (float)j / 31.0f;
    const float a = 1.0f / powf(10000.0f, t);
    const float arg = (float)s * a;
    float sn, cs;
    sincosf(arg, &sn, &cs);

    const size_t base = (((size_t)bh * Sq + s) << 6) + 2*j;
    float q1 = g_q[base], q2 = g_q[base+1];
    g_q[base]   = q1*cs - q2*sn;
    g_q[base+1] = q2*cs + q1*sn;
    float k1 = g_k[base], k2 = g_k[base+1];
    g_k[base]   = k1*cs - k2*sn;
    g_k[base+1] = k2*cs + k1*sn;
}

// ===========================================================================
// Tensor-core retention attention. Block = 64 q-rows of one (b,h), 4 warps.
// Decay folded into Q/K row prescale + per-tile constant:
//   e^{(qi-kj)d} = e^{(qi-q0)d} * e^{(q0-k0)d} * e^{(k0-kj)d}
// S = QK^T via 3-term split-bf16 MMA; P = S*tc (masked); O += P@V (3-term,
// V fragments via ldmatrix.trans from natural [k][d] layout).
// Hardened: kt loop kept rolled (#pragma unroll 1), halved loader registers.
// ===========================================================================
#define RBh 144                       // padded row bytes (72 halves)
#define ATT2_SMEM (6*64*RBh)          // Qh Ql Kh Kl Vh Vl = 55296

__global__ __launch_bounds__(128, 1) void attn_mma_kernel()
{
    extern __shared__ char sm2[];
    const uint32_t sb = smem_u32(sm2);
    const int tid = threadIdx.x, lane = tid & 31, w = tid >> 5;
    const int bh = blockIdx.y, h = bh & (Hq-1);
    const int qb = (int)gridDim.x - 1 - (int)blockIdx.x;   // heavy blocks first
    const int q0 = qb * 64;
    const float decay = log1pf(-exp2f(-(float)(5+h)));
    const size_t gbase = (size_t)bh * Sq * Dq;

    char* Qh = sm2;                  char* Ql = sm2 + 64*RBh;
    char* Kh = sm2 + 2*64*RBh;       char* Kl = sm2 + 3*64*RBh;
    char* Vh = sm2 + 4*64*RBh;       char* Vl = sm2 + 5*64*RBh;
    const uint32_t sKh = sb + 2*64*RBh, sKl = sb + 3*64*RBh;
    const uint32_t sVh = sb + 4*64*RBh, sVl = sb + 5*64*RBh;

    // --- load Q tile, prescale rows by e^{(qi-q0)*decay}, split hi/lo ---
    #pragma unroll
    for (int i = 0; i < 8; i++) {
        const int idx = tid * 8 + i;          // 0..1023
        const int r = idx >> 4, c = (idx & 15) * 4;
        float4 v = *(const float4*)&g_q[gbase + (size_t)(q0 + r)*64 + c];
        const float s = __expf((float)r * decay);
        v.x *= s; v.y *= s; v.z *= s; v.w *= s;
        uint2 hh, ll; split4(v, hh, ll);
        *(uint2*)(Qh + r*RBh + c*2) = hh;
        *(uint2*)(Ql + r*RBh + c*2) = ll;
    }
    __syncthreads();

    // universal ldmatrix lane offset
    const uint32_t loff = (uint32_t)(((lane & 7) + 8*((lane >> 3) & 1)) * RBh
                                     + (lane >> 4) * 16);

    // Q A-fragments (resident for whole block)
    uint32_t qh_f[4][4], ql_f[4][4];
    #pragma unroll
    for (int kf = 0; kf < 4; kf++) {
        LDSM4(qh_f[kf], sb          + (uint32_t)(w*16*RBh + kf*32) + loff);
        LDSM4(ql_f[kf], sb + 64*RBh + (uint32_t)(w*16*RBh + kf*32) + loff);
    }

    float oacc[8][4] = {};
    float dsum0 = 0.f, dsum1 = 0.f;

    #pragma unroll 1
    for (int kt = 0; kt <= qb; kt++) {
        __syncthreads();   // previous tile's MMAs done before overwrite
        #pragma unroll 1
        for (int half = 0; half < 2; half++) {
            #pragma unroll
            for (int i = 0; i < 4; i++) {
                const int idx = (half * 128 + tid) * 4 + i;   // 0..1023
                const int r = idx >> 4, c = (idx & 15) * 4;
                float4 kv = *(const float4*)&g_k[gbase + (size_t)(kt*64 + r)*64 + c];
                const float s = __expf(-(float)r * decay);
                kv.x *= s; kv.y *= s; kv.z *= s; kv.w *= s;
                uint2 hh, ll; split4(kv, hh, ll);
                *(uint2*)(Kh + r*RBh + c*2) = hh;
                *(uint2*)(Kl + r*RBh + c*2) = ll;
                float4 vv = *(const float4*)&g_v[gbase + (size_t)(kt*64 + r)*64 + c];
                split4(vv, hh, ll);
                *(uint2*)(Vh + r*RBh + c*2) = hh;
                *(uint2*)(Vl + r*RBh + c*2) = ll;
            }
        }
        __syncthreads();

        // ---- S = Q K^T (3-term split) ----
        float s_acc[8][4] = {};
        #pragma unroll
        for (int ntp = 0; ntp < 4; ntp++) {
            #pragma unroll
            for (int kf = 0; kf < 4; kf++) {
                const uint32_t o = (uint32_t)(ntp*16*RBh + kf*32) + loff;
                uint32_t bhf[4], blf[4];
                LDSM4(bhf, sKh + o);
                LDSM4(blf, sKl + o);
                MMA16816(s_acc[2*ntp],   qh_f[kf], bhf[0], bhf[2]);
                MMA16816(s_acc[2*ntp+1], qh_f[kf], bhf[1], bhf[3]);
                MMA16816(s_acc[2*ntp],   ql_f[kf], bhf[0], bhf[2]);
                MMA16816(s_acc[2*ntp+1], ql_f[kf], bhf[1], bhf[3]);
                MMA16816(s_acc[2*ntp],   qh_f[kf], blf[0], blf[2]);
                MMA16816(s_acc[2*ntp+1], qh_f[kf], blf[1], blf[3]);
            }
        }

        // ---- tile const, causal mask, |S| accumulation ----
        const float tc = __expf((float)((qb - kt) * 64) * decay);
        const int qi0 = w*16 + (lane >> 2);
        const int cc  = (lane & 3) * 2;
        #pragma unroll
        for (int nt = 0; nt < 8; nt++) {
            float c0 = s_acc[nt][0] * tc, c1 = s_acc[nt][1] * tc;
            float c2 = s_acc[nt][2] * tc, c3 = s_acc[nt][3] * tc;
            if (kt == qb) {
                const int kj = nt*8 + cc;
                if (kj     > qi0)     c0 = 0.f;
                if (kj + 1 > qi0)     c1 = 0.f;
                if (kj     > qi0 + 8) c2 = 0.f;
                if (kj + 1 > qi0 + 8) c3 = 0.f;
            }
            dsum0 += fabsf(c0) + fabsf(c1);
            dsum1 += fabsf(c2) + fabsf(c3);
            s_acc[nt][0] = c0; s_acc[nt][1] = c1;
            s_acc[nt][2] = c2; s_acc[nt][3] = c3;
        }

        // ---- convert S accumulators to P A-fragments (hi/lo) ----
        uint32_t ph[4][4], pl[4][4];
        #pragma unroll
        for (int kf = 0; kf < 4; kf++) {
            split_pair(s_acc[2*kf][0],   s_acc[2*kf][1],   ph[kf][0], pl[kf][0]);
            split_pair(s_acc[2*kf][2],   s_acc[2*kf][3],   ph[kf][1], pl[kf][1]);
            split_pair(s_acc[2*kf+1][0], s_acc[2*kf+1][1], ph[kf][2], pl[kf][2]);
            split_pair(s_acc[2*kf+1][2], s_acc[2*kf+1][3], ph[kf][3], pl[kf][3]);
        }

        // ---- O += P V (3-term split, V via ldmatrix.trans) ----
        #pragma unroll
        for (int dp = 0; dp < 4; dp++) {
            #pragma unroll
            for (int kf = 0; kf < 4; kf++) {
                const uint32_t o = (uint32_t)(kf*16*RBh + dp*32) + loff;
                uint32_t vhf[4], vlf[4];
                LDSM4T(vhf, sVh + o);
                LDSM4T(vlf, sVl + o);
                MMA16816(oacc[2*dp],   ph[kf], vhf[0], vhf[1]);
                MMA16816(oacc[2*dp+1], ph[kf], vhf[2], vhf[3]);
                MMA16816(oacc[2*dp],   pl[kf], vhf[0], vhf[1]);
                MMA16816(oacc[2*dp+1], pl[kf], vhf[2], vhf[3]);
                MMA16816(oacc[2*dp],   ph[kf], vlf[0], vlf[1]);
                MMA16816(oacc[2*dp+1], ph[kf], vlf[2], vlf[3]);
            }
        }
    }

    // ---- row abs-sum reduce across quad lanes ----
    dsum0 += __shfl_xor_sync(0xffffffffu, dsum0, 1);
    dsum0 += __shfl_xor_sync(0xffffffffu, dsum0, 2);
    dsum1 += __shfl_xor_sync(0xffffffffu, dsum1, 1);
    dsum1 += __shfl_xor_sync(0xffffffffu, dsum1, 2);

    const float two_p = exp2f((float)(5 + h));
    const int qa = q0 + w*16 + (lane >> 2);
    const int qb_row = qa + 8;
    const float ga = -expm1f((float)(qa + 1) * decay) * two_p;
    const float gb = -expm1f((float)(qb_row + 1) * decay) * two_p;
    const float ra = rsqrtf(ga), rb2 = rsqrtf(gb);
    float da = fminf(fmaxf(ra * dsum0, 1.0f), 50000.0f);
    float db = fminf(fmaxf(rb2 * dsum1, 1.0f), 50000.0f);
    const float sa = ra / da, sb2 = rb2 / db;

    const int cc = (lane & 3) * 2;
    #pragma unroll
    for (int nt = 0; nt < 8; nt++) {
        const int d = nt*8 + cc;
        *(float2*)&g_o[gbase + (size_t)qa*64 + d] =
            make_float2(oacc[nt][0] * sa, oacc[nt][1] * sa);
        *(float2*)&g_o[gbase + (size_t)qb_row*64 + d] =
            make_float2(oacc[nt][2] * sb2, oacc[nt][3] * sb2);
    }
}

// ---------------------------------------------------------------------------
// Epilogue: per-head RMSNorm over D, gate with silu(g). One warp per (b,s,h).
// ---------------------------------------------------------------------------
__global__ __launch_bounds__(256) void epilogue_kernel(float* __restrict__ out)
{
    const int gid  = blockIdx.x * 8 + (threadIdx.x >> 5);  // 0..65535
    const int lane = threadIdx.x & 31;
    const int h = gid & (Hq-1);
    const int s = (gid >> 4) & (Sq-1);
    const int b = gid >> 15;

    const float* op = &g_o[(((size_t)(b*Hq+h)*Sq) + s) * 64];
    float v1 = op[lane], v2 = op[lane+32];
    float ss = v1*v1 + v2*v2;
    #pragma unroll
    for (int o = 16; o; o >>= 1) ss += __shfl_xor_sync(0xffffffffu, ss, o);
    const float sc = rsqrtf(ss * (1.0f/64.0f) + 1e-6f);

    const size_t ob = ((size_t)(b*Sq + s))*Eq + h*64;
    float gv1 = g_g[ob+lane], gv2 = g_g[ob+lane+32];
    out[ob+lane]    = (gv1 / (1.0f + expf(-gv1))) * v1 * sc;
    out[ob+lane+32] = (gv2 / (1.0f + expf(-gv2))) * v2 * sc;
}

// ---------------------------------------------------------------------------
extern "C" void kernel_launch(void* const* d_in, const int* in_sizes, int n_in,
                              void* d_out, int out_size)
{
    const float* x  = (const float*)d_in[0];
    const float* Wq = (const float*)d_in[1];
    const float* Wk = (const float*)d_in[2];
    const float* Wv = (const float*)d_in[3];
    const float* Wg = (const float*)d_in[4];
    float* out = (float*)d_out;

    cudaFuncSetAttribute(gemm_mma_kernel,
                         cudaFuncAttributeMaxDynamicSharedMemorySize, GEMM_SMEM);
    cudaFuncSetAttribute(attn_mma_kernel,
                         cudaFuncAttributeMaxDynamicSharedMemorySize, ATT2_SMEM);

    transpose_kernel<<<dim3(32, 32, 4), 256>>>(Wq, Wk, Wv, Wg);
    gemm_mma_kernel<<<dim3(Rq/128, Eq/128, 4), 256, GEMM_SMEM>>>(x);
    rotary_kernel<<<(BHq*Sq*32)/256, 256>>>();
    attn_mma_kernel<<<dim3(Sq/64, BHq), 128, ATT2_SMEM>>>();
    epilogue_kernel<<<(Bq*Sq*Hq)/8, 256>>>(out);
}

// round 14
// speedup vs baseline: 3.4038x; 1.3484x over previous
#include <cuda_runtime.h>
#include <cuda_bf16.h>
#include <math.h>
#include <stdint.h>

#define Bq 2
#define Sq 2048
#define Eq 1024
#define Hq 16
#define Dq 64
#define Rq (Bq*Sq)          // 4096 rows of x
#define BHq (Bq*Hq)         // 32

// fp32 scratch
__device__ float g_g[Rq*Eq];       // gate projection [B,S,E]
__device__ float g_o[BHq*Sq*Dq];   // attention out [B,H,S,D]

// split-bf16 precomputed operands (16B aligned for cp.async)
__device__ __align__(16) __nv_bfloat16 g_xh[Rq*Eq],  g_xl[Rq*Eq];
__device__ __align__(16) __nv_bfloat16 g_wth[4*Eq*Eq], g_wtl[4*Eq*Eq];
__device__ __align__(16) __nv_bfloat16 g_qh[BHq*Sq*Dq], g_ql[BHq*Sq*Dq];
__device__ __align__(16) __nv_bfloat16 g_kh[BHq*Sq*Dq], g_kl[BHq*Sq*Dq];
__device__ __align__(16) __nv_bfloat16 g_vh[BHq*Sq*Dq], g_vl[BHq*Sq*Dq];

__device__ __forceinline__ uint32_t smem_u32(const void* p) {
    uint32_t a;
    asm("{ .reg .u64 t; cvta.to.shared.u64 t, %1; cvt.u32.u64 %0, t; }"
        : "=r"(a) : "l"(p));
    return a;
}

#define LDSM4(r, addr) \
    asm volatile("ldmatrix.sync.aligned.m8n8.x4.shared.b16 {%0,%1,%2,%3}, [%4];" \
        : "=r"((r)[0]), "=r"((r)[1]), "=r"((r)[2]), "=r"((r)[3]) : "r"(addr))

#define LDSM4T(r, addr) \
    asm volatile("ldmatrix.sync.aligned.m8n8.x4.trans.shared.b16 {%0,%1,%2,%3}, [%4];" \
        : "=r"((r)[0]), "=r"((r)[1]), "=r"((r)[2]), "=r"((r)[3]) : "r"(addr))

#define MMA16816(c, a, b0, b1) \
    asm volatile("mma.sync.aligned.m16n8k16.row.col.f32.bf16.bf16.f32 " \
        "{%0,%1,%2,%3},{%4,%5,%6,%7},{%8,%9},{%0,%1,%2,%3};" \
        : "+f"((c)[0]), "+f"((c)[1]), "+f"((c)[2]), "+f"((c)[3]) \
        : "r"((a)[0]), "r"((a)[1]), "r"((a)[2]), "r"((a)[3]), "r"(b0), "r"(b1))

#define CP_ASYNC16(dst, src) \
    asm volatile("cp.async.cg.shared.global [%0], [%1], 16;" \
                 :: "r"(dst), "l"(src) : "memory")
#define CP_COMMIT() asm volatile("cp.async.commit_group;" ::: "memory")
#define CP_WAIT0()  asm volatile("cp.async.wait_group 0;" ::: "memory")

__device__ __forceinline__ void split4(float4 v, uint2& h, uint2& l) {
    const float fv[4] = {v.x, v.y, v.z, v.w};
    uint32_t hh[4], ll[4];
    #pragma unroll
    for (int u = 0; u < 4; u++) {
        __nv_bfloat16 bh = __float2bfloat16(fv[u]);
        float res = fv[u] - __bfloat162float(bh);
        __nv_bfloat16 bl = __float2bfloat16(res);
        hh[u] = (uint32_t)__bfloat16_as_ushort(bh);
        ll[u] = (uint32_t)__bfloat16_as_ushort(bl);
    }
    h.x = hh[0] | (hh[1] << 16);  h.y = hh[2] | (hh[3] << 16);
    l.x = ll[0] | (ll[1] << 16);  l.y = ll[2] | (ll[3] << 16);
}

__device__ __forceinline__ void split_pair(float a, float b,
                                           uint32_t& h, uint32_t& l) {
    __nv_bfloat162 hv = __floats2bfloat162_rn(a, b);
    float ra = a - __bfloat162float(hv.x);
    float rb = b - __bfloat162float(hv.y);
    __nv_bfloat162 lv = __floats2bfloat162_rn(ra, rb);
    h = *(uint32_t*)&hv;
    l = *(uint32_t*)&lv;
}

// ===========================================================================
// Prep: split X into hi/lo bf16
// ===========================================================================
__global__ __launch_bounds__(256) void split_x_kernel(const float* __restrict__ X)
{
    const int idx = blockIdx.x * 256 + threadIdx.x;     // 1M float4s
    float4 v = *(const float4*)&X[(size_t)idx * 4];
    uint2 h, l; split4(v, h, l);
    *(uint2*)&g_xh[(size_t)idx * 4] = h;
    *(uint2*)&g_xl[(size_t)idx * 4] = l;
}

// ===========================================================================
// Prep: transpose + split weights: wth/wtl[z][n][k] = split(W[z][k][n])
// ===========================================================================
__global__ __launch_bounds__(256) void transpose_split_kernel(
    const float* __restrict__ Wqp, const float* __restrict__ Wkp,
    const float* __restrict__ Wvp, const float* __restrict__ Wgp)
{
    const int z = blockIdx.z;
    const float* __restrict__ W = (z==0)?Wqp:(z==1)?Wkp:(z==2)?Wvp:Wgp;
    const size_t zb = (size_t)z * Eq * Eq;

    __shared__ float t[32][33];
    const int tx = threadIdx.x & 31, ty = threadIdx.x >> 5;   // 32 x 8
    const int x0 = blockIdx.x * 32, y0 = blockIdx.y * 32;

    #pragma unroll
    for (int r = 0; r < 32; r += 8)
        t[ty + r][tx] = W[(size_t)(y0 + ty + r) * Eq + x0 + tx];
    __syncthreads();
    #pragma unroll
    for (int r = 0; r < 32; r += 8) {
        const float val = t[tx][ty + r];
        __nv_bfloat16 hb = __float2bfloat16(val);
        __nv_bfloat16 lb = __float2bfloat16(val - __bfloat162float(hb));
        const size_t o = zb + (size_t)(x0 + ty + r) * Eq + y0 + tx;
        g_wth[o] = hb;
        g_wtl[o] = lb;
    }
}

// ===========================================================================
// mma.sync split-bf16 GEMM with cp.async double-buffered loader.
// Y[4096,1024] = X @ W[z]; 128x128 CTA tile; SMEM rows 80B (64 data + 16 pad).
// Epilogue fuses rotary + decay prescale + hi/lo split for q,k and split for v
// (each thread's acc pair (c_in, c_in+1) = rotary pair (2j, 2j+1)).
// ===========================================================================
#define TILE_B   10240               // 128*80 bytes
#define BUF_B    (4*TILE_B)          // 40960
#define GEMM_SMEM (2*BUF_B)          // 81920

__device__ __forceinline__ void gemm_load(uint32_t bufb, int row0, int col0,
                                          int w, int c, int tid)
{
    const size_t wb = (size_t)w * Eq * Eq;
    #pragma unroll
    for (int i = 0; i < 8; i++) {
        const int a   = i >> 1;
        const int rem = (i & 1) * 256 + tid;
        const int row = rem >> 2, seg = rem & 3;
        const __nv_bfloat16* src;
        if      (a == 0) src = g_xh  + (size_t)(row0 + row) * Eq + c*32 + seg*8;
        else if (a == 1) src = g_xl  + (size_t)(row0 + row) * Eq + c*32 + seg*8;
        else if (a == 2) src = g_wth + wb + (size_t)(col0 + row) * Eq + c*32 + seg*8;
        else             src = g_wtl + wb + (size_t)(col0 + row) * Eq + c*32 + seg*8;
        CP_ASYNC16(bufb + a*TILE_B + row*80 + seg*16, src);
    }
}

__global__ __launch_bounds__(256) void gemm_mma_kernel()
{
    extern __shared__ char smc[];
    const int tid = threadIdx.x, lane = tid & 31, wrp = tid >> 5;
    const int wm = wrp & 1, wn = wrp >> 1;          // 2x4 warp grid: 64x32 each
    const int row0 = blockIdx.x * 128;
    const int col0 = blockIdx.y * 128;
    const int w    = blockIdx.z;

    const uint32_t sbase = smem_u32(smc);
    const uint32_t aoff = (uint32_t)((wm*64 + (lane & 15)) * 80 + (lane >> 4) * 16);
    const uint32_t boff = (uint32_t)((wn*32 + (lane & 7) + ((lane >> 4) & 1) * 8) * 80
                                     + ((lane >> 3) & 1) * 16);

    float acc[4][4][4] = {};

    gemm_load(sbase, row0, col0, w, 0, tid);
    CP_COMMIT(); CP_WAIT0();
    __syncthreads();

    #pragma unroll 1
    for (int c = 0; c < 32; c++) {
        if (c < 31) {
            gemm_load(sbase + (uint32_t)(((c + 1) & 1) * BUF_B), row0, col0, w, c + 1, tid);
            CP_COMMIT();
        }

        const uint32_t base = sbase + (uint32_t)((c & 1) * BUF_B);
        #pragma unroll
        for (int ks = 0; ks < 2; ks++) {
            const uint32_t ksb = (uint32_t)(ks * 32);
            uint32_t a_h[4][4], a_l[4][4], b_h[4][2], b_l[4][2];
            #pragma unroll
            for (int mt = 0; mt < 4; mt++)
                LDSM4(a_h[mt], base + aoff + mt*1280 + ksb);
            #pragma unroll
            for (int np = 0; np < 2; np++) {
                uint32_t r[4];
                LDSM4(r, base + 2*TILE_B + boff + np*1280 + ksb);
                b_h[2*np][0] = r[0]; b_h[2*np][1] = r[1];
                b_h[2*np+1][0] = r[2]; b_h[2*np+1][1] = r[3];
            }
            #pragma unroll
            for (int mt = 0; mt < 4; mt++)
                #pragma unroll
                for (int nt = 0; nt < 4; nt++)
                    MMA16816(acc[mt][nt], a_h[mt], b_h[nt][0], b_h[nt][1]);

            #pragma unroll
            for (int mt = 0; mt < 4; mt++)
                LDSM4(a_l[mt], base + TILE_B + aoff + mt*1280 + ksb);
            #pragma unroll
            for (int mt = 0; mt < 4; mt++)
                #pragma unroll
                for (int nt = 0; nt < 4; nt++)
                    MMA16816(acc[mt][nt], a_l[mt], b_h[nt][0], b_h[nt][1]);

            #pragma unroll
            for (int np = 0; np < 2; np++) {
                uint32_t r[4];
                LDSM4(r, base + 3*TILE_B + boff + np*1280 + ksb);
                b_l[2*np][0] = r[0]; b_l[2*np][1] = r[1];
                b_l[2*np+1][0] = r[2]; b_l[2*np+1][1] = r[3];
            }
            #pragma unroll
            for (int mt = 0; mt < 4; mt++)
                #pragma unroll
                for (int nt = 0; nt < 4; nt++)
                    MMA16816(acc[mt][nt], a_h[mt], b_l[nt][0], b_l[nt][1]);
        }

        if (c < 31) CP_WAIT0();
        __syncthreads();
    }

    // ---- fused epilogue ----
    const int r_in = lane >> 2;
    const int c_in = (lane & 3) * 2;

    if (w == 3) {
        #pragma unroll
        for (int mt = 0; mt < 4; mt++)
            #pragma unroll
            for (int nt = 0; nt < 4; nt++) {
                const int m0  = row0 + wm*64 + mt*16 + r_in;
                const int col = col0 + wn*32 + nt*8 + c_in;
                *(float2*)&g_g[(size_t)m0 * Eq + col] =
                    make_float2(acc[mt][nt][0], acc[mt][nt][1]);
                *(float2*)&g_g[(size_t)(m0+8) * Eq + col] =
                    make_float2(acc[mt][nt][2], acc[mt][nt][3]);
            }
    } else {
        #pragma unroll
        for (int nt = 0; nt < 4; nt++) {
            const int col = col0 + wn*32 + nt*8 + c_in;
            const int h = col >> 6, d = col & 63;      // d even: rotary pair (d, d+1)
            const float ang = 1.0f / powf(10000.0f, (float)(d >> 1) / 31.0f);
            const float decay = log1pf(-exp2f(-(float)(5 + h)));
            #pragma unroll
            for (int mt = 0; mt < 4; mt++) {
                #pragma unroll
                for (int rr = 0; rr < 2; rr++) {
                    const int m = row0 + wm*64 + mt*16 + r_in + rr*8;
                    const int b0 = m >> 11, s0 = m & (Sq-1);
                    float v0 = acc[mt][nt][2*rr], v1 = acc[mt][nt][2*rr + 1];
                    const size_t gofs = (((size_t)(b0*Hq + h) * Sq + s0) << 6) + d;
                    uint32_t hw, lw;
                    if (w == 2) {
                        split_pair(v0, v1, hw, lw);
                        *(uint32_t*)&g_vh[gofs] = hw;  *(uint32_t*)&g_vl[gofs] = lw;
                    } else {
                        if (w == 1) { v0 *= 0.03125f; v1 *= 0.03125f; }
                        float sn, cs;
                        sincosf((float)s0 * ang, &sn, &cs);
                        const float rloc = (float)(s0 & 63);
                        const float pre = __expf((w == 0 ? rloc : -rloc) * decay);
                        const float r1 = (v0*cs - v1*sn) * pre;
                        const float r2 = (v1*cs + v0*sn) * pre;
                        split_pair(r1, r2, hw, lw);
                        if (w == 0) { *(uint32_t*)&g_qh[gofs] = hw;  *(uint32_t*)&g_ql[gofs] = lw; }
                        else        { *(uint32_t*)&g_kh[gofs] = hw;  *(uint32_t*)&g_kl[gofs] = lw; }
                    }
                }
            }
        }
    }
}

// ===========================================================================
// Tensor-core retention attention with cp.async double-buffered K/V.
// SMEM: Qh,Ql (2 x 9216) + 2 bufs x (Kh,Kl,Vh,Vl) (4 x 9216 each) = 92160.
// ===========================================================================
#define RBh 144                       // padded row bytes (72 halves)
#define ATT_TILE (64*RBh)             // 9216
#define ATT_KVBUF (4*ATT_TILE)        // 36864
#define ATT2_SMEM (2*ATT_TILE + 2*ATT_KVBUF)   // 92160

__device__ __forceinline__ void attn_load_tile(uint32_t bufb, size_t gofs, int tid)
{
    #pragma unroll
    for (int i = 0; i < 16; i++) {
        const int a   = i >> 2;                       // 0=Kh 1=Kl 2=Vh 3=Vl
        const int rem = (i & 3) * 128 + tid;
        const int row = rem >> 3, seg = rem & 7;
        const __nv_bfloat16* src =
            ((a==0) ? g_kh : (a==1) ? g_kl : (a==2) ? g_vh : g_vl)
            + gofs + (size_t)row*64 + seg*8;
        CP_ASYNC16(bufb + a*ATT_TILE + row*144 + seg*16, src);
    }
}

__global__ __launch_bounds__(128, 1) void attn_mma_kernel()
{
    extern __shared__ char sm2[];
    const uint32_t sb = smem_u32(sm2);
    const int tid = threadIdx.x, lane = tid & 31, w = tid >> 5;
    const int bh = blockIdx.y, h = bh & (Hq-1);
    const int qb = (int)gridDim.x - 1 - (int)blockIdx.x;   // heavy blocks first
    const int q0 = qb * 64;
    const float decay = log1pf(-exp2f(-(float)(5+h)));
    const size_t gbase = (size_t)bh * Sq * Dq;

    const uint32_t sQ   = sb;                     // Qh then Ql
    const uint32_t sKV0 = sb + 2*ATT_TILE;

    // --- preload Q (hi+lo) and K/V tile 0 via cp.async ---
    {
        const size_t qofs = gbase + (size_t)q0 * 64;
        #pragma unroll
        for (int i = 0; i < 8; i++) {
            const int a   = i >> 2;               // 0=Qh 1=Ql
            const int rem = (i & 3) * 128 + tid;
            const int row = rem >> 3, seg = rem & 7;
            const __nv_bfloat16* src = ((a==0) ? g_qh : g_ql)
                                       + qofs + (size_t)row*64 + seg*8;
            CP_ASYNC16(sQ + a*ATT_TILE + row*144 + seg*16, src);
        }
        attn_load_tile(sKV0, gbase, tid);
        CP_COMMIT(); CP_WAIT0();
    }
    __syncthreads();

    // universal ldmatrix lane offset
    const uint32_t loff = (uint32_t)(((lane & 7) + 8*((lane >> 3) & 1)) * RBh
                                     + (lane >> 4) * 16);

    // Q A-fragments (resident for whole block)
    uint32_t qh_f[4][4], ql_f[4][4];
    #pragma unroll
    for (int kf = 0; kf < 4; kf++) {
        LDSM4(qh_f[kf], sQ            + (uint32_t)(w*16*RBh + kf*32) + loff);
        LDSM4(ql_f[kf], sQ + ATT_TILE + (uint32_t)(w*16*RBh + kf*32) + loff);
    }

    float oacc[8][4] = {};
    float dsum0 = 0.f, dsum1 = 0.f;

    #pragma unroll 1
    for (int kt = 0; kt <= qb; kt++) {
        if (kt < qb) {
            attn_load_tile(sKV0 + (uint32_t)(((kt + 1) & 1) * ATT_KVBUF),
                           gbase + (size_t)(kt + 1) * 64 * 64, tid);
            CP_COMMIT();
        }
        const uint32_t kvb = sKV0 + (uint32_t)((kt & 1) * ATT_KVBUF);
        const uint32_t sKh = kvb, sKl = kvb + ATT_TILE;
        const uint32_t sVh = kvb + 2*ATT_TILE, sVl = kvb + 3*ATT_TILE;

        // ---- S = Q K^T (3-term split) ----
        float s_acc[8][4] = {};
        #pragma unroll
        for (int ntp = 0; ntp < 4; ntp++) {
            #pragma unroll
            for (int kf = 0; kf < 4; kf++) {
                const uint32_t o = (uint32_t)(ntp*16*RBh + kf*32) + loff;
                uint32_t bhf[4], blf[4];
                LDSM4(bhf, sKh + o);
                LDSM4(blf, sKl + o);
                MMA16816(s_acc[2*ntp],   qh_f[kf], bhf[0], bhf[2]);
                MMA16816(s_acc[2*ntp+1], qh_f[kf], bhf[1], bhf[3]);
                MMA16816(s_acc[2*ntp],   ql_f[kf], bhf[0], bhf[2]);
                MMA16816(s_acc[2*ntp+1], ql_f[kf], bhf[1], bhf[3]);
                MMA16816(s_acc[2*ntp],   qh_f[kf], blf[0], blf[2]);
                MMA16816(s_acc[2*ntp+1], qh_f[kf], blf[1], blf[3]);
            }
        }

        // ---- tile const, causal mask, |S| accumulation ----
        const float tc = __expf((float)((qb - kt) * 64) * decay);
        const int qi0 = w*16 + (lane >> 2);
        const int cc  = (lane & 3) * 2;
        #pragma unroll
        for (int nt = 0; nt < 8; nt++) {
            float c0 = s_acc[nt][0] * tc, c1 = s_acc[nt][1] * tc;
            float c2 = s_acc[nt][2] * tc, c3 = s_acc[nt][3] * tc;
            if (kt == qb) {
                const int kj = nt*8 + cc;
                if (kj     > qi0)     c0 = 0.f;
                if (kj + 1 > qi0)     c1 = 0.f;
                if (kj     > qi0 + 8) c2 = 0.f;
                if (kj + 1 > qi0 + 8) c3 = 0.f;
            }
            dsum0 += fabsf(c0) + fabsf(c1);
            dsum1 += fabsf(c2) + fabsf(c3);
            s_acc[nt][0] = c0; s_acc[nt][1] = c1;
            s_acc[nt][2] = c2; s_acc[nt][3] = c3;
        }

        // ---- convert S accumulators to P A-fragments (hi/lo) ----
        uint32_t ph[4][4], pl[4][4];
        #pragma unroll
        for (int kf = 0; kf < 4; kf++) {
            split_pair(s_acc[2*kf][0],   s_acc[2*kf][1],   ph[kf][0], pl[kf][0]);
            split_pair(s_acc[2*kf][2],   s_acc[2*kf][3],   ph[kf][1], pl[kf][1]);
            split_pair(s_acc[2*kf+1][0], s_acc[2*kf+1][1], ph[kf][2], pl[kf][2]);
            split_pair(s_acc[2*kf+1][2], s_acc[2*kf+1][3], ph[kf][3], pl[kf][3]);
        }

        // ---- O += P V (3-term split, V via ldmatrix.trans) ----
        #pragma unroll
        for (int dp = 0; dp < 4; dp++) {
            #pragma unroll
            for (int kf = 0; kf < 4; kf++) {
                const uint32_t o = (uint32_t)(kf*16*RBh + dp*32) + loff;
                uint32_t vhf[4], vlf[4];
                LDSM4T(vhf, sVh + o);
                LDSM4T(vlf, sVl + o);
                MMA16816(oacc[2*dp],   ph[kf], vhf[0], vhf[1]);
                MMA16816(oacc[2*dp+1], ph[kf], vhf[2], vhf[3]);
                MMA16816(oacc[2*dp],   pl[kf], vhf[0], vhf[1]);
                MMA16816(oacc[2*dp+1], pl[kf], vhf[2], vhf[3]);
                MMA16816(oacc[2*dp],   ph[kf], vlf[0], vlf[1]);
                MMA16816(oacc[2*dp+1], ph[kf], vlf[2], vlf[3]);
            }
        }

        if (kt < qb) CP_WAIT0();
        __syncthreads();
    }

    // ---- row abs-sum reduce across quad lanes ----
    dsum0 += __shfl_xor_sync(0xffffffffu, dsum0, 1);
    dsum0 += __shfl_xor_sync(0xffffffffu, dsum0, 2);
    dsum1 += __shfl_xor_sync(0xffffffffu, dsum1, 1);
    dsum1 += __shfl_xor_sync(0xffffffffu, dsum1, 2);

    const float two_p = exp2f((float)(5 + h));
    const int qa = q0 + w*16 + (lane >> 2);
    const int qb_row = qa + 8;
    const float ga = -expm1f((float)(qa + 1) * decay) * two_p;
    const float gb = -expm1f((float)(qb_row + 1) * decay) * two_p;
    const float ra = rsqrtf(ga), rb2 = rsqrtf(gb);
    float da = fminf(fmaxf(ra * dsum0, 1.0f), 50000.0f);
    float db = fminf(fmaxf(rb2 * dsum1, 1.0f), 50000.0f);
    const float sa = ra / da, sb2 = rb2 / db;

    const int cc = (lane & 3) * 2;
    #pragma unroll
    for (int nt = 0; nt < 8; nt++) {
        const int d = nt*8 + cc;
        *(float2*)&g_o[gbase + (size_t)qa*64 + d] =
            make_float2(oacc[nt][0] * sa, oacc[nt][1] * sa);
        *(float2*)&g_o[gbase + (size_t)qb_row*64 + d] =
            make_float2(oacc[nt][2] * sb2, oacc[nt][3] * sb2);
    }
}

// ---------------------------------------------------------------------------
// Epilogue: per-head RMSNorm over D, gate with silu(g). One warp per (b,s,h).
// ---------------------------------------------------------------------------
__global__ __launch_bounds__(256) void epilogue_kernel(float* __restrict__ out)
{
    const int gid  = blockIdx.x * 8 + (threadIdx.x >> 5);  // 0..65535
    const int lane = threadIdx.x & 31;
    const int h = gid & (Hq-1);
    const int s = (gid >> 4) & (Sq-1);
    const int b = gid >> 15;

    const float* op = &g_o[(((size_t)(b*Hq+h)*Sq) + s) * 64];
    float v1 = op[lane], v2 = op[lane+32];
    float ss = v1*v1 + v2*v2;
    #pragma unroll
    for (int o = 16; o; o >>= 1) ss += __shfl_xor_sync(0xffffffffu, ss, o);
    const float sc = rsqrtf(ss * (1.0f/64.0f) + 1e-6f);

    const size_t ob = ((size_t)(b*Sq + s))*Eq + h*64;
    float gv1 = g_g[ob+lane], gv2 = g_g[ob+lane+32];
    out[ob+lane]    = (gv1 / (1.0f + expf(-gv1))) * v1 * sc;
    out[ob+lane+32] = (gv2 / (1.0f + expf(-gv2))) * v2 * sc;
}

// ---------------------------------------------------------------------------
extern "C" void kernel_launch(void* const* d_in, const int* in_sizes, int n_in,
                              void* d_out, int out_size)
{
    const float* x  = (const float*)d_in[0];
    const float* Wq = (const float*)d_in[1];
    const float* Wk = (const float*)d_in[2];
    const float* Wv = (const float*)d_in[3];
    const float* Wg = (const float*)d_in[4];
    float* out = (float*)d_out;

    cudaFuncSetAttribute(gemm_mma_kernel,
                         cudaFuncAttributeMaxDynamicSharedMemorySize, GEMM_SMEM);
    cudaFuncSetAttribute(attn_mma_kernel,
                         cudaFuncAttributeMaxDynamicSharedMemorySize, ATT2_SMEM);

    split_x_kernel<<<Rq*Eq/1024, 256>>>(x);
    transpose_split_kernel<<<dim3(32, 32, 4), 256>>>(Wq, Wk, Wv, Wg);
    gemm_mma_kernel<<<dim3(Rq/128, Eq/128, 4), 256, GEMM_SMEM>>>();
    attn_mma_kernel<<<dim3(Sq/64, BHq), 128, ATT2_SMEM>>>();
    epilogue_kernel<<<(Bq*Sq*Hq)/8, 256>>>(out);
}